// round 1
// baseline (speedup 1.0000x reference)
#include <cuda_runtime.h>
#include <math.h>

// Problem dims (fixed)
#define Bb 2
#define Ss 2048
#define Ee 1024
#define Hh 16
#define Dd 64
#define Mm (Bb * Ss)      // 4096
#define HD (Hh * Dd)      // 1024

// Scratch (allocation-free: static device globals)
__device__ float g_Q[Mm * HD];
__device__ float g_K[Mm * HD];
__device__ float g_V[Mm * HD];
__device__ float g_C[Mm * HD];

// ---------------------------------------------------------------------------
// Classic 128x128x8 register-tiled SGEMM, 256 threads, 8x8 per thread.
// A: row-major [M,K].
// bmode 0: B row-major [K,N]
// bmode 1: B is [H, K, 64] (per-head weight [H,E,D] with D=64); col n -> head n>>6
// C: row-major [M,N]. All dims divisible by tiles (M%128==0, N%128==0, K%8==0).
// ---------------------------------------------------------------------------
__global__ __launch_bounds__(256) void sgemm128(
    const float* __restrict__ A, const float* __restrict__ Bm,
    float* __restrict__ C, int M, int N, int K, int bmode)
{
    __shared__ float As[8][128];   // As[k][m] (transposed)
    __shared__ float Bs[8][128];   // Bs[k][n]

    const int tid = threadIdx.x;
    const int m0 = blockIdx.y * 128;
    const int n0 = blockIdx.x * 128;

    const int aRow = tid >> 1;            // 0..127
    const int aCol = (tid & 1) << 2;      // 0 or 4
    const int bRow = tid >> 5;            // 0..7
    const int bCol = (tid & 31) << 2;     // 0..124

    const int tRow = (tid >> 4) << 3;     // 0..120
    const int tCol = (tid & 15) << 3;     // 0..120

    const float* Ag = A + (size_t)(m0 + aRow) * K + aCol;

    const int n = n0 + bCol;
    const float* Bg;
    int bstep;
    if (bmode == 0) {
        Bg = Bm + (size_t)bRow * N + n;
        bstep = 8 * N;
    } else {
        Bg = Bm + (size_t)(n >> 6) * K * 64 + (size_t)bRow * 64 + (n & 63);
        bstep = 8 * 64;
    }

    float acc[8][8];
    #pragma unroll
    for (int i = 0; i < 8; i++)
        #pragma unroll
        for (int j = 0; j < 8; j++) acc[i][j] = 0.0f;

    for (int k0 = 0; k0 < K; k0 += 8) {
        float4 av = *(const float4*)Ag;
        Ag += 8;
        As[aCol + 0][aRow] = av.x;
        As[aCol + 1][aRow] = av.y;
        As[aCol + 2][aRow] = av.z;
        As[aCol + 3][aRow] = av.w;

        float4 bv = *(const float4*)Bg;
        Bg += bstep;
        *(float4*)&Bs[bRow][bCol] = bv;

        __syncthreads();

        #pragma unroll
        for (int kk = 0; kk < 8; kk++) {
            float rm[8], rn[8];
            *(float4*)&rm[0] = *(const float4*)&As[kk][tRow];
            *(float4*)&rm[4] = *(const float4*)&As[kk][tRow + 4];
            *(float4*)&rn[0] = *(const float4*)&Bs[kk][tCol];
            *(float4*)&rn[4] = *(const float4*)&Bs[kk][tCol + 4];
            #pragma unroll
            for (int i = 0; i < 8; i++)
                #pragma unroll
                for (int j = 0; j < 8; j++)
                    acc[i][j] += rm[i] * rn[j];
        }
        __syncthreads();
    }

    #pragma unroll
    for (int i = 0; i < 8; i++) {
        float4 v0 = make_float4(acc[i][0], acc[i][1], acc[i][2], acc[i][3]);
        float4 v1 = make_float4(acc[i][4], acc[i][5], acc[i][6], acc[i][7]);
        float* Cp = C + (size_t)(m0 + tRow + i) * N + n0 + tCol;
        *(float4*)(Cp) = v0;
        *(float4*)(Cp + 4) = v1;
    }
}

// ---------------------------------------------------------------------------
// Flash attention, fp32. One block per (q-tile of 64, head, batch).
// Q,K,V stored [B, S, H*D] row-major; output ctx stored [B, S, H*D].
// scores scaled by 1/Dd (reference divides by D, not sqrt(D)).
// Thread layout: 16x16, each thread owns 4 score-rows x 4 cols and a 4x4 O tile.
// ---------------------------------------------------------------------------
#define AST 68   // padded smem stride (floats), multiple of 4 for float4 align

__global__ __launch_bounds__(256) void attn64(
    const float* __restrict__ Q, const float* __restrict__ K,
    const float* __restrict__ V, float* __restrict__ O)
{
    extern __shared__ float sm[];
    float* Qt = sm;                 // Qt[d][r], stride AST
    float* Kt = sm + 64 * AST;      // Kt[d][c], stride AST
    float* Ps = sm + 2 * 64 * AST;  // Ps[i][j], stride AST
    float* Vs = sm + 3 * 64 * AST;  // Vs[j][d], stride 64

    const int tid = threadIdx.x;
    const int b = blockIdx.z, h = blockIdx.y;
    const int q0 = blockIdx.x * 64;
    const int ty = tid >> 4, tx = tid & 15;
    const int r0 = ty << 2, c0 = tx << 2;

    const float* Qg = Q + ((size_t)(b * Ss + q0)) * HD + h * Dd;
    const float* Kg = K + (size_t)b * Ss * HD + h * Dd;
    const float* Vg = V + (size_t)b * Ss * HD + h * Dd;

    // Load Q tile, transposed to Qt[d][r]
    for (int idx = tid; idx < 64 * 16; idx += 256) {
        int r = idx >> 4, d4 = (idx & 15) << 2;
        float4 v = *(const float4*)(Qg + (size_t)r * HD + d4);
        Qt[(d4 + 0) * AST + r] = v.x;
        Qt[(d4 + 1) * AST + r] = v.y;
        Qt[(d4 + 2) * AST + r] = v.z;
        Qt[(d4 + 3) * AST + r] = v.w;
    }

    float m_i[4], l_i[4], o[4][4];
    #pragma unroll
    for (int i = 0; i < 4; i++) {
        m_i[i] = -1e30f;
        l_i[i] = 0.0f;
        #pragma unroll
        for (int j = 0; j < 4; j++) o[i][j] = 0.0f;
    }

    const float sc = 1.0f / (float)Dd;

    for (int kt = 0; kt < Ss; kt += 64) {
        __syncthreads();  // (A) prior-iter reads of Kt/Vs/Ps done; Qt visible on iter 0

        // Load K tile transposed (Kt[d][c]) and V tile natural (Vs[j][d])
        for (int idx = tid; idx < 64 * 16; idx += 256) {
            int r = idx >> 4, d4 = (idx & 15) << 2;
            float4 kv = *(const float4*)(Kg + (size_t)(kt + r) * HD + d4);
            Kt[(d4 + 0) * AST + r] = kv.x;
            Kt[(d4 + 1) * AST + r] = kv.y;
            Kt[(d4 + 2) * AST + r] = kv.z;
            Kt[(d4 + 3) * AST + r] = kv.w;
            float4 vv = *(const float4*)(Vg + (size_t)(kt + r) * HD + d4);
            *(float4*)&Vs[r * 64 + d4] = vv;
        }
        __syncthreads();  // (B)

        // s[4][4] = Q Kt
        float s[4][4];
        #pragma unroll
        for (int i = 0; i < 4; i++)
            #pragma unroll
            for (int j = 0; j < 4; j++) s[i][j] = 0.0f;

        #pragma unroll 8
        for (int d = 0; d < 64; d++) {
            float4 qv = *(const float4*)&Qt[d * AST + r0];
            float4 kv = *(const float4*)&Kt[d * AST + c0];
            float qr[4] = {qv.x, qv.y, qv.z, qv.w};
            float kr[4] = {kv.x, kv.y, kv.z, kv.w};
            #pragma unroll
            for (int i = 0; i < 4; i++)
                #pragma unroll
                for (int j = 0; j < 4; j++)
                    s[i][j] += qr[i] * kr[j];
        }

        // online softmax per row (rows owned by ty; reduce across the 16 tx lanes)
        #pragma unroll
        for (int i = 0; i < 4; i++) {
            #pragma unroll
            for (int j = 0; j < 4; j++) s[i][j] *= sc;
            float mr = fmaxf(fmaxf(s[i][0], s[i][1]), fmaxf(s[i][2], s[i][3]));
            #pragma unroll
            for (int off = 8; off > 0; off >>= 1)
                mr = fmaxf(mr, __shfl_xor_sync(0xffffffffu, mr, off));
            float mn = fmaxf(m_i[i], mr);
            float corr = __expf(m_i[i] - mn);
            float sum = 0.0f;
            #pragma unroll
            for (int j = 0; j < 4; j++) {
                s[i][j] = __expf(s[i][j] - mn);
                sum += s[i][j];
            }
            #pragma unroll
            for (int off = 8; off > 0; off >>= 1)
                sum += __shfl_xor_sync(0xffffffffu, sum, off);
            l_i[i] = l_i[i] * corr + sum;
            m_i[i] = mn;
            #pragma unroll
            for (int j = 0; j < 4; j++) o[i][j] *= corr;
            *(float4*)&Ps[(r0 + i) * AST + c0] =
                make_float4(s[i][0], s[i][1], s[i][2], s[i][3]);
        }
        __syncthreads();  // (C) Ps visible

        // O += P @ V   (reduce over j; thread owns rows r0..r0+3, d-cols c0..c0+3)
        #pragma unroll 4
        for (int j = 0; j < 64; j += 4) {
            float pr[4][4];
            #pragma unroll
            for (int i = 0; i < 4; i++)
                *(float4*)pr[i] = *(const float4*)&Ps[(r0 + i) * AST + j];
            #pragma unroll
            for (int t = 0; t < 4; t++) {
                float4 vv = *(const float4*)&Vs[(j + t) * 64 + c0];
                float vr[4] = {vv.x, vv.y, vv.z, vv.w};
                #pragma unroll
                for (int i = 0; i < 4; i++)
                    #pragma unroll
                    for (int u = 0; u < 4; u++)
                        o[i][u] += pr[i][t] * vr[u];
            }
        }
    }

    // epilogue: O / l  -> ctx[b][s][h*64+d]
    #pragma unroll
    for (int i = 0; i < 4; i++) {
        float inv = 1.0f / l_i[i];
        float4 v = make_float4(o[i][0] * inv, o[i][1] * inv,
                               o[i][2] * inv, o[i][3] * inv);
        *(float4*)(O + ((size_t)(b * Ss + q0 + r0 + i)) * HD + h * Dd + c0) = v;
    }
}

#define ATTN_SMEM ((3 * 64 * AST + 64 * 64) * (int)sizeof(float))  // 68608 B

extern "C" void kernel_launch(void* const* d_in, const int* in_sizes, int n_in,
                              void* d_out, int out_size)
{
    const float* x  = (const float*)d_in[0];
    const float* Wq = (const float*)d_in[1];
    const float* Wk = (const float*)d_in[2];
    const float* Wv = (const float*)d_in[3];
    const float* Wo = (const float*)d_in[4];
    float* out = (float*)d_out;

    float *q, *k, *v, *c;
    cudaGetSymbolAddress((void**)&q, g_Q);
    cudaGetSymbolAddress((void**)&k, g_K);
    cudaGetSymbolAddress((void**)&v, g_V);
    cudaGetSymbolAddress((void**)&c, g_C);

    cudaFuncSetAttribute(attn64, cudaFuncAttributeMaxDynamicSharedMemorySize,
                         ATTN_SMEM);

    dim3 gqkv(HD / 128, Mm / 128);   // (8, 32)
    sgemm128<<<gqkv, 256>>>(x, Wq, q, Mm, HD, Ee, 1);
    sgemm128<<<gqkv, 256>>>(x, Wk, k, Mm, HD, Ee, 1);
    sgemm128<<<gqkv, 256>>>(x, Wv, v, Mm, HD, Ee, 1);

    dim3 ga(Ss / 64, Hh, Bb);        // (32, 16, 2)
    attn64<<<ga, 256, ATTN_SMEM>>>(q, k, v, c);

    dim3 go(Ee / 128, Mm / 128);     // (8, 32)
    sgemm128<<<go, 256>>>(c, Wo, out, Mm, Ee, HD, 0);
}

// round 3
// speedup vs baseline: 1.4238x; 1.4238x over previous
#include <cuda_runtime.h>
#include <cuda_bf16.h>
#include <cstdint>
#include <math.h>

// Problem dims (fixed)
#define Bb 2
#define Ss 2048
#define Ee 1024
#define Hh 16
#define Dd 64
#define Mm (Bb * Ss)      // 4096
#define HD (Hh * Dd)      // 1024

// ---------------------------------------------------------------------------
// Scratch (allocation-free static device globals)
// ---------------------------------------------------------------------------
__device__ float g_Q[Mm * HD];
__device__ float g_K[Mm * HD];
__device__ float g_V[Mm * HD];
__device__ __nv_bfloat16 g_Xhi[Mm * Ee], g_Xlo[Mm * Ee];
__device__ __nv_bfloat16 g_Whi[4][Ee * HD], g_Wlo[4][Ee * HD]; // [n][k] transposed
__device__ __nv_bfloat16 g_Chi[Mm * HD], g_Clo[Mm * HD];

__device__ __forceinline__ uint32_t smem_u32(const void* p) {
    uint32_t a;
    asm("{ .reg .u64 t; cvta.to.shared.u64 t, %1; cvt.u32.u64 %0, t; }" : "=r"(a) : "l"(p));
    return a;
}
__device__ __forceinline__ void ldsm4(uint32_t* r, uint32_t addr) {
    asm volatile("ldmatrix.sync.aligned.m8n8.x4.shared.b16 {%0,%1,%2,%3}, [%4];"
        : "=r"(r[0]), "=r"(r[1]), "=r"(r[2]), "=r"(r[3]) : "r"(addr));
}
__device__ __forceinline__ void mma16816(float* c, const uint32_t* a, const uint32_t* b) {
    asm volatile(
        "mma.sync.aligned.m16n8k16.row.col.f32.bf16.bf16.f32 "
        "{%0,%1,%2,%3}, {%4,%5,%6,%7}, {%8,%9}, {%0,%1,%2,%3};"
        : "+f"(c[0]), "+f"(c[1]), "+f"(c[2]), "+f"(c[3])
        : "r"(a[0]), "r"(a[1]), "r"(a[2]), "r"(a[3]), "r"(b[0]), "r"(b[1]));
}

// ---------------------------------------------------------------------------
// Split / transpose prep kernels
// ---------------------------------------------------------------------------
__global__ __launch_bounds__(256) void split_plain(
    const float4* __restrict__ X, __nv_bfloat162* __restrict__ hi,
    __nv_bfloat162* __restrict__ lo, int n4)
{
    int i = blockIdx.x * 256 + threadIdx.x;
    if (i >= n4) return;
    float4 v = X[i];
    float a[4] = {v.x, v.y, v.z, v.w};
    __nv_bfloat16 h[4], l[4];
    #pragma unroll
    for (int j = 0; j < 4; j++) {
        h[j] = __float2bfloat16(a[j]);
        l[j] = __float2bfloat16(a[j] - __bfloat162float(h[j]));
    }
    hi[2 * i]     = __nv_bfloat162(h[0], h[1]);
    hi[2 * i + 1] = __nv_bfloat162(h[2], h[3]);
    lo[2 * i]     = __nv_bfloat162(l[0], l[1]);
    lo[2 * i + 1] = __nv_bfloat162(l[2], l[3]);
}

// mode 0: In [1024 x 1024] row-major, out[n][k] = In[k][n]  (Wo)
// mode 1: In [16][1024][64],          out[n][k] = In[n>>6][k][n&63]  (Wq/Wk/Wv)
__global__ __launch_bounds__(256) void trans_split(
    const float* __restrict__ In, __nv_bfloat16* __restrict__ Ohi,
    __nv_bfloat16* __restrict__ Olo, int mode)
{
    __shared__ float t[32][33];
    int k0 = blockIdx.x * 32, n0 = blockIdx.y * 32;
    int tx = threadIdx.x & 31, ty = threadIdx.x >> 5;   // 32 x 8
    #pragma unroll
    for (int r = 0; r < 32; r += 8) {
        int k = k0 + ty + r, n = n0 + tx;
        float v = (mode == 0) ? In[(size_t)k * 1024 + n]
                              : In[(size_t)(n >> 6) * 65536 + (size_t)k * 64 + (n & 63)];
        t[ty + r][tx] = v;
    }
    __syncthreads();
    #pragma unroll
    for (int r = 0; r < 32; r += 8) {
        int n = n0 + ty + r, k = k0 + tx;
        float v = t[tx][ty + r];
        __nv_bfloat16 hh = __float2bfloat16(v);
        Ohi[(size_t)n * 1024 + k] = hh;
        Olo[(size_t)n * 1024 + k] = __float2bfloat16(v - __bfloat162float(hh));
    }
}

// ---------------------------------------------------------------------------
// mma.sync bf16 split GEMM: C = (Ahi+Alo)(Bhi+Blo)^T, lo*lo dropped.
// Block tile 128x128x32, 8 warps (2x4 -> 64x32 each), 2-stage cp.async.
// Smem rows padded to 80B (conflict-free ldmatrix).
// ---------------------------------------------------------------------------
#define MAT_B   10240              // 128 rows * 80 bytes
#define STAGE_B (4 * MAT_B)        // Ahi, Alo, Bhi, Blo
#define G_SMEM  (2 * STAGE_B)      // 81920

__device__ __forceinline__ void g_load_stage(
    uint32_t stage_base, int kc,
    const __nv_bfloat16* Ahi, const __nv_bfloat16* Alo,
    const __nv_bfloat16* Bhi, const __nv_bfloat16* Blo,
    int m0, int n0, int K, int tid)
{
    const __nv_bfloat16* srcs[4] = {
        Ahi + (size_t)m0 * K + kc * 32,
        Alo + (size_t)m0 * K + kc * 32,
        Bhi + (size_t)n0 * K + kc * 32,
        Blo + (size_t)n0 * K + kc * 32 };
    #pragma unroll
    for (int j = 0; j < 8; j++) {
        int id = tid + j * 256;            // 0..2047
        int mat = id >> 9;                 // 512 chunks per matrix
        int rid = (id & 511) >> 2;         // row 0..127
        int c   = id & 3;                  // 16B chunk 0..3
        uint32_t dst = stage_base + mat * MAT_B + rid * 80 + c * 16;
        const void* src = srcs[mat] + (size_t)rid * K + c * 8;
        asm volatile("cp.async.cg.shared.global [%0], [%1], 16;" :: "r"(dst), "l"(src));
    }
    asm volatile("cp.async.commit_group;" ::: "memory");
}

__global__ __launch_bounds__(256) void gemm_tc(
    const __nv_bfloat16* __restrict__ Ahi, const __nv_bfloat16* __restrict__ Alo,
    const __nv_bfloat16* __restrict__ Bhi, const __nv_bfloat16* __restrict__ Blo,
    float* __restrict__ C, int M, int N, int K)
{
    extern __shared__ char smem[];
    uint32_t sb = smem_u32(smem);
    const int tid = threadIdx.x;
    const int wid = tid >> 5, lane = tid & 31;
    const int wm = (wid >> 2) * 64;        // warp m offset (0 / 64)
    const int wn = (wid & 3) * 32;         // warp n offset (0/32/64/96)
    const int m0 = blockIdx.y * 128, n0 = blockIdx.x * 128;
    const int nk = K / 32;

    g_load_stage(sb, 0, Ahi, Alo, Bhi, Blo, m0, n0, K, tid);
    g_load_stage(sb + STAGE_B, 1, Ahi, Alo, Bhi, Blo, m0, n0, K, tid);

    float acc[4][4][4];
    #pragma unroll
    for (int i = 0; i < 4; i++)
        #pragma unroll
        for (int j = 0; j < 4; j++)
            #pragma unroll
            for (int t = 0; t < 4; t++) acc[i][j][t] = 0.0f;

    // ldmatrix lane address components
    const int arow = lane & 15;
    const int acol = (lane >> 4) << 3;                 // 0 or 8
    const int brow = ((lane >> 4) << 3) + (lane & 7);  // n within 16
    const int bcol = ((lane >> 3) & 1) << 3;           // 0 or 8

    for (int kc = 0; kc < nk; kc++) {
        if (kc < nk - 1) asm volatile("cp.async.wait_group 1;" ::: "memory");
        else             asm volatile("cp.async.wait_group 0;" ::: "memory");
        __syncthreads();

        uint32_t st = sb + (kc & 1) * STAGE_B;
        uint32_t sAhi = st, sAlo = st + MAT_B, sBhi = st + 2 * MAT_B, sBlo = st + 3 * MAT_B;

        #pragma unroll
        for (int ks = 0; ks < 2; ks++) {
            uint32_t ah[4][4], al[4][4], bh[2][4], bl[2][4];
            #pragma unroll
            for (int i = 0; i < 4; i++) {
                uint32_t off = (uint32_t)(wm + i * 16 + arow) * 80 + (ks * 16 + acol) * 2;
                ldsm4(ah[i], sAhi + off);
                ldsm4(al[i], sAlo + off);
            }
            #pragma unroll
            for (int p = 0; p < 2; p++) {
                uint32_t off = (uint32_t)(wn + p * 16 + brow) * 80 + (ks * 16 + bcol) * 2;
                ldsm4(bh[p], sBhi + off);
                ldsm4(bl[p], sBlo + off);
            }
            #pragma unroll
            for (int i = 0; i < 4; i++)
                #pragma unroll
                for (int j = 0; j < 4; j++) {
                    mma16816(acc[i][j], ah[i], &bh[j >> 1][(j & 1) * 2]);
                    mma16816(acc[i][j], ah[i], &bl[j >> 1][(j & 1) * 2]);
                    mma16816(acc[i][j], al[i], &bh[j >> 1][(j & 1) * 2]);
                }
        }
        __syncthreads();
        if (kc + 2 < nk)
            g_load_stage(sb + (kc & 1) * STAGE_B, kc + 2, Ahi, Alo, Bhi, Blo, m0, n0, K, tid);
    }

    // epilogue: fragment -> gmem (row-major C)
    const int er = m0 + wm + (lane >> 2);
    const int ec = n0 + wn + (lane & 3) * 2;
    #pragma unroll
    for (int i = 0; i < 4; i++)
        #pragma unroll
        for (int j = 0; j < 4; j++) {
            float* p0 = C + (size_t)(er + i * 16) * N + ec + j * 8;
            float* p1 = C + (size_t)(er + i * 16 + 8) * N + ec + j * 8;
            *(float2*)p0 = make_float2(acc[i][j][0], acc[i][j][1]);
            *(float2*)p1 = make_float2(acc[i][j][2], acc[i][j][3]);
        }
}

// ---------------------------------------------------------------------------
// Flash attention, fp32 SIMT, emits ctx as hi/lo bf16 split.
// ---------------------------------------------------------------------------
#define AST 68

__global__ __launch_bounds__(256) void attn64(
    const float* __restrict__ Q, const float* __restrict__ K,
    const float* __restrict__ V, __nv_bfloat16* __restrict__ Chi,
    __nv_bfloat16* __restrict__ Clo)
{
    extern __shared__ float sm[];
    float* Qt = sm;
    float* Kt = sm + 64 * AST;
    float* Ps = sm + 2 * 64 * AST;
    float* Vs = sm + 3 * 64 * AST;

    const int tid = threadIdx.x;
    const int b = blockIdx.z, h = blockIdx.y;
    const int q0 = blockIdx.x * 64;
    const int ty = tid >> 4, tx = tid & 15;
    const int r0 = ty << 2, c0 = tx << 2;

    const float* Qg = Q + ((size_t)(b * Ss + q0)) * HD + h * Dd;
    const float* Kg = K + (size_t)b * Ss * HD + h * Dd;
    const float* Vg = V + (size_t)b * Ss * HD + h * Dd;

    for (int idx = tid; idx < 64 * 16; idx += 256) {
        int r = idx >> 4, d4 = (idx & 15) << 2;
        float4 v = *(const float4*)(Qg + (size_t)r * HD + d4);
        Qt[(d4 + 0) * AST + r] = v.x;
        Qt[(d4 + 1) * AST + r] = v.y;
        Qt[(d4 + 2) * AST + r] = v.z;
        Qt[(d4 + 3) * AST + r] = v.w;
    }

    float m_i[4], l_i[4], o[4][4];
    #pragma unroll
    for (int i = 0; i < 4; i++) {
        m_i[i] = -1e30f; l_i[i] = 0.0f;
        #pragma unroll
        for (int j = 0; j < 4; j++) o[i][j] = 0.0f;
    }
    const float sc = 1.0f / (float)Dd;

    for (int kt = 0; kt < Ss; kt += 64) {
        __syncthreads();
        for (int idx = tid; idx < 64 * 16; idx += 256) {
            int r = idx >> 4, d4 = (idx & 15) << 2;
            float4 kv = *(const float4*)(Kg + (size_t)(kt + r) * HD + d4);
            Kt[(d4 + 0) * AST + r] = kv.x;
            Kt[(d4 + 1) * AST + r] = kv.y;
            Kt[(d4 + 2) * AST + r] = kv.z;
            Kt[(d4 + 3) * AST + r] = kv.w;
            float4 vv = *(const float4*)(Vg + (size_t)(kt + r) * HD + d4);
            *(float4*)&Vs[r * 64 + d4] = vv;
        }
        __syncthreads();

        float s[4][4];
        #pragma unroll
        for (int i = 0; i < 4; i++)
            #pragma unroll
            for (int j = 0; j < 4; j++) s[i][j] = 0.0f;

        #pragma unroll 8
        for (int d = 0; d < 64; d++) {
            float4 qv = *(const float4*)&Qt[d * AST + r0];
            float4 kv = *(const float4*)&Kt[d * AST + c0];
            float qr[4] = {qv.x, qv.y, qv.z, qv.w};
            float kr[4] = {kv.x, kv.y, kv.z, kv.w};
            #pragma unroll
            for (int i = 0; i < 4; i++)
                #pragma unroll
                for (int j = 0; j < 4; j++)
                    s[i][j] += qr[i] * kr[j];
        }

        #pragma unroll
        for (int i = 0; i < 4; i++) {
            #pragma unroll
            for (int j = 0; j < 4; j++) s[i][j] *= sc;
            float mr = fmaxf(fmaxf(s[i][0], s[i][1]), fmaxf(s[i][2], s[i][3]));
            #pragma unroll
            for (int off = 8; off > 0; off >>= 1)
                mr = fmaxf(mr, __shfl_xor_sync(0xffffffffu, mr, off));
            float mn = fmaxf(m_i[i], mr);
            float corr = __expf(m_i[i] - mn);
            float sum = 0.0f;
            #pragma unroll
            for (int j = 0; j < 4; j++) { s[i][j] = __expf(s[i][j] - mn); sum += s[i][j]; }
            #pragma unroll
            for (int off = 8; off > 0; off >>= 1)
                sum += __shfl_xor_sync(0xffffffffu, sum, off);
            l_i[i] = l_i[i] * corr + sum;
            m_i[i] = mn;
            #pragma unroll
            for (int j = 0; j < 4; j++) o[i][j] *= corr;
            *(float4*)&Ps[(r0 + i) * AST + c0] =
                make_float4(s[i][0], s[i][1], s[i][2], s[i][3]);
        }
        __syncthreads();

        #pragma unroll 4
        for (int j = 0; j < 64; j += 4) {
            float pr[4][4];
            #pragma unroll
            for (int i = 0; i < 4; i++)
                *(float4*)pr[i] = *(const float4*)&Ps[(r0 + i) * AST + j];
            #pragma unroll
            for (int t = 0; t < 4; t++) {
                float4 vv = *(const float4*)&Vs[(j + t) * 64 + c0];
                float vr[4] = {vv.x, vv.y, vv.z, vv.w};
                #pragma unroll
                for (int i = 0; i < 4; i++)
                    #pragma unroll
                    for (int u = 0; u < 4; u++)
                        o[i][u] += pr[i][t] * vr[u];
            }
        }
    }

    #pragma unroll
    for (int i = 0; i < 4; i++) {
        float inv = 1.0f / l_i[i];
        size_t off = ((size_t)(b * Ss + q0 + r0 + i)) * HD + h * Dd + c0;
        #pragma unroll
        for (int u = 0; u < 4; u++) {
            float val = o[i][u] * inv;
            __nv_bfloat16 hh = __float2bfloat16(val);
            Chi[off + u] = hh;
            Clo[off + u] = __float2bfloat16(val - __bfloat162float(hh));
        }
    }
}

#define ATTN_SMEM ((3 * 64 * AST + 64 * 64) * (int)sizeof(float))

extern "C" void kernel_launch(void* const* d_in, const int* in_sizes, int n_in,
                              void* d_out, int out_size)
{
    const float* x  = (const float*)d_in[0];
    const float* Wq = (const float*)d_in[1];
    const float* Wk = (const float*)d_in[2];
    const float* Wv = (const float*)d_in[3];
    const float* Wo = (const float*)d_in[4];
    float* out = (float*)d_out;

    float *q, *k, *v;
    __nv_bfloat16 *xhi, *xlo, *whi, *wlo, *chi, *clo;
    cudaGetSymbolAddress((void**)&q, g_Q);
    cudaGetSymbolAddress((void**)&k, g_K);
    cudaGetSymbolAddress((void**)&v, g_V);
    cudaGetSymbolAddress((void**)&xhi, g_Xhi);
    cudaGetSymbolAddress((void**)&xlo, g_Xlo);
    cudaGetSymbolAddress((void**)&whi, g_Whi);
    cudaGetSymbolAddress((void**)&wlo, g_Wlo);
    cudaGetSymbolAddress((void**)&chi, g_Chi);
    cudaGetSymbolAddress((void**)&clo, g_Clo);

    cudaFuncSetAttribute(attn64, cudaFuncAttributeMaxDynamicSharedMemorySize, ATTN_SMEM);
    cudaFuncSetAttribute(gemm_tc, cudaFuncAttributeMaxDynamicSharedMemorySize, G_SMEM);

    const int WSZ = Ee * HD;

    split_plain<<<(Mm * Ee / 4 + 255) / 256, 256>>>((const float4*)x,
        (__nv_bfloat162*)xhi, (__nv_bfloat162*)xlo, Mm * Ee / 4);
    dim3 gt(32, 32);
    trans_split<<<gt, 256>>>(Wq, whi + 0 * WSZ, wlo + 0 * WSZ, 1);
    trans_split<<<gt, 256>>>(Wk, whi + 1 * WSZ, wlo + 1 * WSZ, 1);
    trans_split<<<gt, 256>>>(Wv, whi + 2 * WSZ, wlo + 2 * WSZ, 1);
    trans_split<<<gt, 256>>>(Wo, whi + 3 * WSZ, wlo + 3 * WSZ, 0);

    dim3 gg(HD / 128, Mm / 128); // (8, 32)
    gemm_tc<<<gg, 256, G_SMEM>>>(xhi, xlo, whi + 0 * WSZ, wlo + 0 * WSZ, q, Mm, HD, Ee);
    gemm_tc<<<gg, 256, G_SMEM>>>(xhi, xlo, whi + 1 * WSZ, wlo + 1 * WSZ, k, Mm, HD, Ee);
    gemm_tc<<<gg, 256, G_SMEM>>>(xhi, xlo, whi + 2 * WSZ, wlo + 2 * WSZ, v, Mm, HD, Ee);

    dim3 ga(Ss / 64, Hh, Bb);
    attn64<<<ga, 256, ATTN_SMEM>>>(q, k, v, chi, clo);

    dim3 go(Ee / 128, Mm / 128);
    gemm_tc<<<go, 256, G_SMEM>>>(chi, clo, whi + 3 * WSZ, wlo + 3 * WSZ, out, Mm, Ee, HD);
}

// round 4
// speedup vs baseline: 1.4246x; 1.0005x over previous
#include <cuda_runtime.h>
#include <cuda_bf16.h>
#include <cstdint>
#include <math.h>

// Problem dims (fixed)
#define Bb 2
#define Ss 2048
#define Ee 1024
#define Hh 16
#define Dd 64
#define Mm (Bb * Ss)      // 4096
#define HD (Hh * Dd)      // 1024

// ---------------------------------------------------------------------------
// Scratch (allocation-free static device globals)
// ---------------------------------------------------------------------------
__device__ float g_Q[Mm * HD];
__device__ float g_K[Mm * HD];
__device__ float g_V[Mm * HD];
__device__ __nv_bfloat16 g_Xhi[Mm * Ee], g_Xlo[Mm * Ee];
__device__ __nv_bfloat16 g_Whi[4][Ee * HD], g_Wlo[4][Ee * HD]; // [n][k] transposed
__device__ __nv_bfloat16 g_Chi[Mm * HD], g_Clo[Mm * HD];

__device__ __forceinline__ uint32_t smem_u32(const void* p) {
    uint32_t a;
    asm("{ .reg .u64 t; cvta.to.shared.u64 t, %1; cvt.u32.u64 %0, t; }" : "=r"(a) : "l"(p));
    return a;
}
__device__ __forceinline__ void ldsm4(uint32_t* r, uint32_t addr) {
    asm volatile("ldmatrix.sync.aligned.m8n8.x4.shared.b16 {%0,%1,%2,%3}, [%4];"
        : "=r"(r[0]), "=r"(r[1]), "=r"(r[2]), "=r"(r[3]) : "r"(addr));
}
__device__ __forceinline__ void mma16816(float* c, const uint32_t* a, const uint32_t* b) {
    asm volatile(
        "mma.sync.aligned.m16n8k16.row.col.f32.bf16.bf16.f32 "
        "{%0,%1,%2,%3}, {%4,%5,%6,%7}, {%8,%9}, {%0,%1,%2,%3};"
        : "+f"(c[0]), "+f"(c[1]), "+f"(c[2]), "+f"(c[3])
        : "r"(a[0]), "r"(a[1]), "r"(a[2]), "r"(a[3]), "r"(b[0]), "r"(b[1]));
}

// ---------------------------------------------------------------------------
// Split / transpose prep kernels
// ---------------------------------------------------------------------------
__global__ __launch_bounds__(256) void split_plain(
    const float4* __restrict__ X, __nv_bfloat162* __restrict__ hi,
    __nv_bfloat162* __restrict__ lo, int n4)
{
    int i = blockIdx.x * 256 + threadIdx.x;
    if (i >= n4) return;
    float4 v = X[i];
    float a[4] = {v.x, v.y, v.z, v.w};
    __nv_bfloat16 h[4], l[4];
    #pragma unroll
    for (int j = 0; j < 4; j++) {
        h[j] = __float2bfloat16(a[j]);
        l[j] = __float2bfloat16(a[j] - __bfloat162float(h[j]));
    }
    hi[2 * i]     = __nv_bfloat162(h[0], h[1]);
    hi[2 * i + 1] = __nv_bfloat162(h[2], h[3]);
    lo[2 * i]     = __nv_bfloat162(l[0], l[1]);
    lo[2 * i + 1] = __nv_bfloat162(l[2], l[3]);
}

// mode 0: In [1024 x 1024] row-major, out[n][k] = In[k][n]  (Wo)
// mode 1: In [16][1024][64],          out[n][k] = In[n>>6][k][n&63]  (Wq/Wk/Wv)
__global__ __launch_bounds__(256) void trans_split(
    const float* __restrict__ In, __nv_bfloat16* __restrict__ Ohi,
    __nv_bfloat16* __restrict__ Olo, int mode)
{
    __shared__ float t[32][33];
    int k0 = blockIdx.x * 32, n0 = blockIdx.y * 32;
    int tx = threadIdx.x & 31, ty = threadIdx.x >> 5;   // 32 x 8
    #pragma unroll
    for (int r = 0; r < 32; r += 8) {
        int k = k0 + ty + r, n = n0 + tx;
        float v = (mode == 0) ? In[(size_t)k * 1024 + n]
                              : In[(size_t)(n >> 6) * 65536 + (size_t)k * 64 + (n & 63)];
        t[ty + r][tx] = v;
    }
    __syncthreads();
    #pragma unroll
    for (int r = 0; r < 32; r += 8) {
        int n = n0 + ty + r, k = k0 + tx;
        float v = t[tx][ty + r];
        __nv_bfloat16 hh = __float2bfloat16(v);
        Ohi[(size_t)n * 1024 + k] = hh;
        Olo[(size_t)n * 1024 + k] = __float2bfloat16(v - __bfloat162float(hh));
    }
}

// ---------------------------------------------------------------------------
// mma.sync bf16 split GEMM: C = (Ahi+Alo)(Bhi+Blo)^T, lo*lo dropped.
// Block tile 128x128x32, 8 warps (2x4 -> 64x32 each), 2-stage cp.async.
// Smem rows padded to 80B (conflict-free ldmatrix).
// ---------------------------------------------------------------------------
#define MAT_B   10240              // 128 rows * 80 bytes
#define STAGE_B (4 * MAT_B)        // Ahi, Alo, Bhi, Blo
#define G_SMEM  (2 * STAGE_B)      // 81920

__device__ __forceinline__ void g_load_stage(
    uint32_t stage_base, int kc,
    const __nv_bfloat16* Ahi, const __nv_bfloat16* Alo,
    const __nv_bfloat16* Bhi, const __nv_bfloat16* Blo,
    int m0, int n0, int K, int tid)
{
    const __nv_bfloat16* srcs[4] = {
        Ahi + (size_t)m0 * K + kc * 32,
        Alo + (size_t)m0 * K + kc * 32,
        Bhi + (size_t)n0 * K + kc * 32,
        Blo + (size_t)n0 * K + kc * 32 };
    #pragma unroll
    for (int j = 0; j < 8; j++) {
        int id = tid + j * 256;            // 0..2047
        int mat = id >> 9;                 // 512 chunks per matrix
        int rid = (id & 511) >> 2;         // row 0..127
        int c   = id & 3;                  // 16B chunk 0..3
        uint32_t dst = stage_base + mat * MAT_B + rid * 80 + c * 16;
        const void* src = srcs[mat] + (size_t)rid * K + c * 8;
        asm volatile("cp.async.cg.shared.global [%0], [%1], 16;" :: "r"(dst), "l"(src));
    }
    asm volatile("cp.async.commit_group;" ::: "memory");
}

__global__ __launch_bounds__(256) void gemm_tc(
    const __nv_bfloat16* __restrict__ Ahi, const __nv_bfloat16* __restrict__ Alo,
    const __nv_bfloat16* __restrict__ Bhi, const __nv_bfloat16* __restrict__ Blo,
    float* __restrict__ C, int M, int N, int K)
{
    extern __shared__ char smem[];
    uint32_t sb = smem_u32(smem);
    const int tid = threadIdx.x;
    const int wid = tid >> 5, lane = tid & 31;
    const int wm = (wid >> 2) * 64;        // warp m offset (0 / 64)
    const int wn = (wid & 3) * 32;         // warp n offset (0/32/64/96)
    const int m0 = blockIdx.y * 128, n0 = blockIdx.x * 128;
    const int nk = K / 32;

    g_load_stage(sb, 0, Ahi, Alo, Bhi, Blo, m0, n0, K, tid);
    g_load_stage(sb + STAGE_B, 1, Ahi, Alo, Bhi, Blo, m0, n0, K, tid);

    float acc[4][4][4];
    #pragma unroll
    for (int i = 0; i < 4; i++)
        #pragma unroll
        for (int j = 0; j < 4; j++)
            #pragma unroll
            for (int t = 0; t < 4; t++) acc[i][j][t] = 0.0f;

    // ldmatrix lane address components
    const int arow = lane & 15;
    const int acol = (lane >> 4) << 3;                 // 0 or 8
    const int brow = ((lane >> 4) << 3) + (lane & 7);  // n within 16
    const int bcol = ((lane >> 3) & 1) << 3;           // 0 or 8

    for (int kc = 0; kc < nk; kc++) {
        if (kc < nk - 1) asm volatile("cp.async.wait_group 1;" ::: "memory");
        else             asm volatile("cp.async.wait_group 0;" ::: "memory");
        __syncthreads();

        uint32_t st = sb + (kc & 1) * STAGE_B;
        uint32_t sAhi = st, sAlo = st + MAT_B, sBhi = st + 2 * MAT_B, sBlo = st + 3 * MAT_B;

        #pragma unroll
        for (int ks = 0; ks < 2; ks++) {
            uint32_t ah[4][4], al[4][4], bh[2][4], bl[2][4];
            #pragma unroll
            for (int i = 0; i < 4; i++) {
                uint32_t off = (uint32_t)(wm + i * 16 + arow) * 80 + (ks * 16 + acol) * 2;
                ldsm4(ah[i], sAhi + off);
                ldsm4(al[i], sAlo + off);
            }
            #pragma unroll
            for (int p = 0; p < 2; p++) {
                uint32_t off = (uint32_t)(wn + p * 16 + brow) * 80 + (ks * 16 + bcol) * 2;
                ldsm4(bh[p], sBhi + off);
                ldsm4(bl[p], sBlo + off);
            }
            #pragma unroll
            for (int i = 0; i < 4; i++)
                #pragma unroll
                for (int j = 0; j < 4; j++) {
                    mma16816(acc[i][j], ah[i], &bh[j >> 1][(j & 1) * 2]);
                    mma16816(acc[i][j], ah[i], &bl[j >> 1][(j & 1) * 2]);
                    mma16816(acc[i][j], al[i], &bh[j >> 1][(j & 1) * 2]);
                }
        }
        __syncthreads();
        if (kc + 2 < nk)
            g_load_stage(sb + (kc & 1) * STAGE_B, kc + 2, Ahi, Alo, Bhi, Blo, m0, n0, K, tid);
    }

    // epilogue: fragment -> gmem (row-major C)
    const int er = m0 + wm + (lane >> 2);
    const int ec = n0 + wn + (lane & 3) * 2;
    #pragma unroll
    for (int i = 0; i < 4; i++)
        #pragma unroll
        for (int j = 0; j < 4; j++) {
            float* p0 = C + (size_t)(er + i * 16) * N + ec + j * 8;
            float* p1 = C + (size_t)(er + i * 16 + 8) * N + ec + j * 8;
            *(float2*)p0 = make_float2(acc[i][j][0], acc[i][j][1]);
            *(float2*)p1 = make_float2(acc[i][j][2], acc[i][j][3]);
        }
}

// ---------------------------------------------------------------------------
// Flash attention, fp32 SIMT, emits ctx as hi/lo bf16 split.
// ---------------------------------------------------------------------------
#define AST 68

__global__ __launch_bounds__(256) void attn64(
    const float* __restrict__ Q, const float* __restrict__ K,
    const float* __restrict__ V, __nv_bfloat16* __restrict__ Chi,
    __nv_bfloat16* __restrict__ Clo)
{
    extern __shared__ float sm[];
    float* Qt = sm;
    float* Kt = sm + 64 * AST;
    float* Ps = sm + 2 * 64 * AST;
    float* Vs = sm + 3 * 64 * AST;

    const int tid = threadIdx.x;
    const int b = blockIdx.z, h = blockIdx.y;
    const int q0 = blockIdx.x * 64;
    const int ty = tid >> 4, tx = tid & 15;
    const int r0 = ty << 2, c0 = tx << 2;

    const float* Qg = Q + ((size_t)(b * Ss + q0)) * HD + h * Dd;
    const float* Kg = K + (size_t)b * Ss * HD + h * Dd;
    const float* Vg = V + (size_t)b * Ss * HD + h * Dd;

    for (int idx = tid; idx < 64 * 16; idx += 256) {
        int r = idx >> 4, d4 = (idx & 15) << 2;
        float4 v = *(const float4*)(Qg + (size_t)r * HD + d4);
        Qt[(d4 + 0) * AST + r] = v.x;
        Qt[(d4 + 1) * AST + r] = v.y;
        Qt[(d4 + 2) * AST + r] = v.z;
        Qt[(d4 + 3) * AST + r] = v.w;
    }

    float m_i[4], l_i[4], o[4][4];
    #pragma unroll
    for (int i = 0; i < 4; i++) {
        m_i[i] = -1e30f; l_i[i] = 0.0f;
        #pragma unroll
        for (int j = 0; j < 4; j++) o[i][j] = 0.0f;
    }
    const float sc = 1.0f / (float)Dd;

    for (int kt = 0; kt < Ss; kt += 64) {
        __syncthreads();
        for (int idx = tid; idx < 64 * 16; idx += 256) {
            int r = idx >> 4, d4 = (idx & 15) << 2;
            float4 kv = *(const float4*)(Kg + (size_t)(kt + r) * HD + d4);
            Kt[(d4 + 0) * AST + r] = kv.x;
            Kt[(d4 + 1) * AST + r] = kv.y;
            Kt[(d4 + 2) * AST + r] = kv.z;
            Kt[(d4 + 3) * AST + r] = kv.w;
            float4 vv = *(const float4*)(Vg + (size_t)(kt + r) * HD + d4);
            *(float4*)&Vs[r * 64 + d4] = vv;
        }
        __syncthreads();

        float s[4][4];
        #pragma unroll
        for (int i = 0; i < 4; i++)
            #pragma unroll
            for (int j = 0; j < 4; j++) s[i][j] = 0.0f;

        #pragma unroll 8
        for (int d = 0; d < 64; d++) {
            float4 qv = *(const float4*)&Qt[d * AST + r0];
            float4 kv = *(const float4*)&Kt[d * AST + c0];
            float qr[4] = {qv.x, qv.y, qv.z, qv.w};
            float kr[4] = {kv.x, kv.y, kv.z, kv.w};
            #pragma unroll
            for (int i = 0; i < 4; i++)
                #pragma unroll
                for (int j = 0; j < 4; j++)
                    s[i][j] += qr[i] * kr[j];
        }

        #pragma unroll
        for (int i = 0; i < 4; i++) {
            #pragma unroll
            for (int j = 0; j < 4; j++) s[i][j] *= sc;
            float mr = fmaxf(fmaxf(s[i][0], s[i][1]), fmaxf(s[i][2], s[i][3]));
            #pragma unroll
            for (int off = 8; off > 0; off >>= 1)
                mr = fmaxf(mr, __shfl_xor_sync(0xffffffffu, mr, off));
            float mn = fmaxf(m_i[i], mr);
            float corr = __expf(m_i[i] - mn);
            float sum = 0.0f;
            #pragma unroll
            for (int j = 0; j < 4; j++) { s[i][j] = __expf(s[i][j] - mn); sum += s[i][j]; }
            #pragma unroll
            for (int off = 8; off > 0; off >>= 1)
                sum += __shfl_xor_sync(0xffffffffu, sum, off);
            l_i[i] = l_i[i] * corr + sum;
            m_i[i] = mn;
            #pragma unroll
            for (int j = 0; j < 4; j++) o[i][j] *= corr;
            *(float4*)&Ps[(r0 + i) * AST + c0] =
                make_float4(s[i][0], s[i][1], s[i][2], s[i][3]);
        }
        __syncthreads();

        #pragma unroll 4
        for (int j = 0; j < 64; j += 4) {
            float pr[4][4];
            #pragma unroll
            for (int i = 0; i < 4; i++)
                *(float4*)pr[i] = *(const float4*)&Ps[(r0 + i) * AST + j];
            #pragma unroll
            for (int t = 0; t < 4; t++) {
                float4 vv = *(const float4*)&Vs[(j + t) * 64 + c0];
                float vr[4] = {vv.x, vv.y, vv.z, vv.w};
                #pragma unroll
                for (int i = 0; i < 4; i++)
                    #pragma unroll
                    for (int u = 0; u < 4; u++)
                        o[i][u] += pr[i][t] * vr[u];
            }
        }
    }

    #pragma unroll
    for (int i = 0; i < 4; i++) {
        float inv = 1.0f / l_i[i];
        size_t off = ((size_t)(b * Ss + q0 + r0 + i)) * HD + h * Dd + c0;
        #pragma unroll
        for (int u = 0; u < 4; u++) {
            float val = o[i][u] * inv;
            __nv_bfloat16 hh = __float2bfloat16(val);
            Chi[off + u] = hh;
            Clo[off + u] = __float2bfloat16(val - __bfloat162float(hh));
        }
    }
}

#define ATTN_SMEM ((3 * 64 * AST + 64 * 64) * (int)sizeof(float))

extern "C" void kernel_launch(void* const* d_in, const int* in_sizes, int n_in,
                              void* d_out, int out_size)
{
    const float* x  = (const float*)d_in[0];
    const float* Wq = (const float*)d_in[1];
    const float* Wk = (const float*)d_in[2];
    const float* Wv = (const float*)d_in[3];
    const float* Wo = (const float*)d_in[4];
    float* out = (float*)d_out;

    float *q, *k, *v;
    __nv_bfloat16 *xhi, *xlo, *whi, *wlo, *chi, *clo;
    cudaGetSymbolAddress((void**)&q, g_Q);
    cudaGetSymbolAddress((void**)&k, g_K);
    cudaGetSymbolAddress((void**)&v, g_V);
    cudaGetSymbolAddress((void**)&xhi, g_Xhi);
    cudaGetSymbolAddress((void**)&xlo, g_Xlo);
    cudaGetSymbolAddress((void**)&whi, g_Whi);
    cudaGetSymbolAddress((void**)&wlo, g_Wlo);
    cudaGetSymbolAddress((void**)&chi, g_Chi);
    cudaGetSymbolAddress((void**)&clo, g_Clo);

    cudaFuncSetAttribute(attn64, cudaFuncAttributeMaxDynamicSharedMemorySize, ATTN_SMEM);
    cudaFuncSetAttribute(gemm_tc, cudaFuncAttributeMaxDynamicSharedMemorySize, G_SMEM);

    const int WSZ = Ee * HD;

    split_plain<<<(Mm * Ee / 4 + 255) / 256, 256>>>((const float4*)x,
        (__nv_bfloat162*)xhi, (__nv_bfloat162*)xlo, Mm * Ee / 4);
    dim3 gt(32, 32);
    trans_split<<<gt, 256>>>(Wq, whi + 0 * WSZ, wlo + 0 * WSZ, 1);
    trans_split<<<gt, 256>>>(Wk, whi + 1 * WSZ, wlo + 1 * WSZ, 1);
    trans_split<<<gt, 256>>>(Wv, whi + 2 * WSZ, wlo + 2 * WSZ, 1);
    trans_split<<<gt, 256>>>(Wo, whi + 3 * WSZ, wlo + 3 * WSZ, 0);

    dim3 gg(HD / 128, Mm / 128); // (8, 32)
    gemm_tc<<<gg, 256, G_SMEM>>>(xhi, xlo, whi + 0 * WSZ, wlo + 0 * WSZ, q, Mm, HD, Ee);
    gemm_tc<<<gg, 256, G_SMEM>>>(xhi, xlo, whi + 1 * WSZ, wlo + 1 * WSZ, k, Mm, HD, Ee);
    gemm_tc<<<gg, 256, G_SMEM>>>(xhi, xlo, whi + 2 * WSZ, wlo + 2 * WSZ, v, Mm, HD, Ee);

    dim3 ga(Ss / 64, Hh, Bb);
    attn64<<<ga, 256, ATTN_SMEM>>>(q, k, v, chi, clo);

    dim3 go(Ee / 128, Mm / 128);
    gemm_tc<<<go, 256, G_SMEM>>>(chi, clo, whi + 3 * WSZ, wlo + 3 * WSZ, out, Mm, Ee, HD);
}